// round 3
// baseline (speedup 1.0000x reference)
#include <cuda_runtime.h>
#include <math.h>

#define Bq 4
#define Nn 500
#define Dd 2048
#define Kk 50
#define H0 28
#define C0c 512
#define NP0 (H0*H0)
#define H1 14
#define C1c 1024
#define NP1 (H1*H1)
#define IMG 224
#define KS 33
#define RAD 16

#define KCH0 10
#define KPW0 5
#define KCH1 25
#define KPW1 2
#define BLK0 ((Bq*NP0*KCH0)/8)   // 3920
#define BLK1 ((Bq*NP1*KCH1)/8)   // 2450

#define DIST_BLKS ((Bq*Nn*32 + 255)/256)   // 250

// ---------------- device scratch ----------------
__device__ float    g_d2[Bq*Nn];
__device__ int      g_idx[Bq*Kk];
__device__ unsigned g_min0[Bq*NP0];
__device__ unsigned g_min1[Bq*NP1];
__device__ float    g_C0[IMG*H0];    // composite blur*resize operator, level 0
__device__ float    g_C1[IMG*H1];
__device__ float    g_T0[Bq*IMG*H0]; // after vertical pass
__device__ float    g_T1[Bq*IMG*H1];

// reflect-101 (single reflection; RAD < IMG)
__device__ __forceinline__ int reflect(int i) {
    if (i < 0) return -i;
    if (i > IMG - 1) return 2*(IMG - 1) - i;
    return i;
}

// ---------------- pairwise distances + composite-operator precompute ----------------
// blocks [0, DIST_BLKS): one warp per (b, n) distance
// blocks DIST_BLKS, DIST_BLKS+1: build C = Blur(33-tap, reflect101) * BilinearUp(H->224)
__global__ void dist_kernel(const float* __restrict__ x2,
                            const float* __restrict__ f2) {
    if (blockIdx.x < DIST_BLKS) {
        int gw = (blockIdx.x * blockDim.x + threadIdx.x) >> 5;
        int lane = threadIdx.x & 31;
        if (gw >= Bq * Nn) return;
        int b = gw / Nn, n = gw % Nn;
        const float4* q = (const float4*)(x2 + (size_t)b * Dd);
        const float4* f = (const float4*)(f2 + (size_t)n * Dd);
        float ss = 0.f;
        #pragma unroll
        for (int j = 0; j < 16; j++) {
            float4 a = q[lane + j*32];
            float4 c = f[lane + j*32];
            float dx = a.x - c.x, dy = a.y - c.y, dz = a.z - c.z, dw = a.w - c.w;
            ss += dx*dx + dy*dy + dz*dz + dw*dw;
        }
        #pragma unroll
        for (int o = 16; o; o >>= 1) ss += __shfl_xor_sync(0xFFFFFFFFu, ss, o);
        if (lane == 0) g_d2[gw] = ss;
        return;
    }
    // ----- operator precompute -----
    int lvl = blockIdx.x - DIST_BLKS;          // 0 or 1
    int H = lvl ? H1 : H0;
    float* Cm = lvl ? g_C1 : g_C0;
    int y = threadIdx.x;
    if (y >= IMG) return;
    // normalized gaussian weights (computed per thread, trivial)
    float w[KS];
    float wsum = 0.f;
    #pragma unroll
    for (int o = 0; o < KS; o++) {
        float xx = (float)o - (float)RAD;
        w[o] = expf(-(xx*xx) / (2.0f * 4.0f * 4.0f));
        wsum += w[o];
    }
    __shared__ float sC[IMG * H0];             // max 224*28 floats
    float* row = sC + y * H;
    for (int i = 0; i < H; i++) row[i] = 0.f;
    float scale = (float)H / (float)IMG;
    #pragma unroll
    for (int o = 0; o < KS; o++) {
        int t = reflect(y + o - RAD);
        float fy = ((float)t + 0.5f) * scale - 0.5f;
        float f0 = floorf(fy);
        float wf = fy - f0;
        int i0 = (int)f0;
        int i0c = max(i0, 0), i1c = min(i0 + 1, H - 1);
        float ww = w[o] / wsum;
        row[i0c] += ww * (1.f - wf);
        row[i1c] += ww * wf;
    }
    for (int i = 0; i < H; i++) Cm[y * H + i] = row[i];
}

// ---------------- select top-K + score + init scratch ----------------
__global__ void select_kernel(float* __restrict__ out_score) {
    int b = blockIdx.x;
    int tid = threadIdx.x;
    __shared__ float sd[Nn];
    __shared__ float ssel[Kk];
    for (int i = tid; i < NP0; i += 256) g_min0[b*NP0 + i] = 0x7F800000u;
    for (int i = tid; i < NP1; i += 256) g_min1[b*NP1 + i] = 0x7F800000u;
    for (int n = tid; n < Nn; n += 256) sd[n] = g_d2[b*Nn + n];
    __syncthreads();
    for (int n = tid; n < Nn; n += 256) {
        float dn = sd[n];
        int r = 0;
        for (int m = 0; m < Nn; m++) {
            float dm = sd[m];
            r += (dm < dn) || (dm == dn && m < n);
        }
        if (r < Kk) { g_idx[b*Kk + r] = n; ssel[r] = sqrtf(fmaxf(dn, 0.f)); }
    }
    __syncthreads();
    if (tid == 0) {
        float s = 0.f;
        for (int i = 0; i < Kk; i++) s += ssel[i];
        out_score[b] = s / (float)Kk;
    }
}

// ---------------- min-distance maps (HBM-bound) ----------------
template<int C, int NP, int KCH, int KPW>
__device__ __forceinline__ void minmap_body(const float* __restrict__ x,
                                            const float* __restrict__ f,
                                            unsigned* __restrict__ gmin,
                                            int wid, int lane) {
    int chunk = wid % KCH;
    int pix   = (wid / KCH) % NP;
    int b     = wid / (KCH * NP);

    int nn[KPW];
    #pragma unroll
    for (int kk = 0; kk < KPW; kk++) nn[kk] = g_idx[b*Kk + chunk*KPW + kk];

    float part[KPW];
    #pragma unroll
    for (int kk = 0; kk < KPW; kk++) part[kk] = 0.f;

    constexpr int NCH = C / 512;
    #pragma unroll
    for (int cc = 0; cc < NCH; cc++) {
        const float4* xv = (const float4*)(x + ((size_t)(b*NP + pix))*C + cc*512);
        float4 xr[4];
        #pragma unroll
        for (int r = 0; r < 4; r++) xr[r] = xv[lane + r*32];
        #pragma unroll
        for (int kk = 0; kk < KPW; kk++) {
            const float4* fv = (const float4*)(f + ((size_t)nn[kk]*NP + pix)*C + cc*512);
            #pragma unroll
            for (int r = 0; r < 4; r++) {
                float4 v = fv[lane + r*32];
                float dx = v.x - xr[r].x, dy = v.y - xr[r].y;
                float dz = v.z - xr[r].z, dw = v.w - xr[r].w;
                part[kk] += dx*dx + dy*dy + dz*dz + dw*dw;
            }
        }
    }
    #pragma unroll
    for (int kk = 0; kk < KPW; kk++) {
        #pragma unroll
        for (int o = 16; o; o >>= 1)
            part[kk] += __shfl_xor_sync(0xFFFFFFFFu, part[kk], o);
    }
    float mn = part[0];
    #pragma unroll
    for (int kk = 1; kk < KPW; kk++) mn = fminf(mn, part[kk]);
    if (lane == 0) atomicMin(gmin + b*NP + pix, __float_as_uint(mn));
}

__global__ void minmap_fused(const float* __restrict__ x0, const float* __restrict__ f0,
                             const float* __restrict__ x1, const float* __restrict__ f1) {
    int lane = threadIdx.x & 31;
    int wIn  = threadIdx.x >> 5;
    if (blockIdx.x < BLK0) {
        int wid = blockIdx.x * 8 + wIn;
        minmap_body<C0c, NP0, KCH0, KPW0>(x0, f0, g_min0, wid, lane);
    } else {
        int wid = (blockIdx.x - BLK0) * 8 + wIn;
        minmap_body<C1c, NP1, KCH1, KPW1>(x1, f1, g_min1, wid, lane);
    }
}

// ---------------- vertical pass: T[b,y,i] = sum_t C[y,t] * sqrt(min[b,t,i]) ----------------
#define NE0 (Bq*IMG*H0)
#define NE1 (Bq*IMG*H1)
__global__ void vpass_kernel() {
    int t = blockIdx.x * blockDim.x + threadIdx.x;
    if (t < NE0) {
        int i = t % H0;
        int y = (t / H0) % IMG;
        int b = t / (H0 * IMG);
        const unsigned* m = g_min0 + b * NP0;
        const float* Crow = g_C0 + y * H0;
        float s = 0.f;
        #pragma unroll 7
        for (int tt = 0; tt < H0; tt++)
            s += Crow[tt] * sqrtf(__uint_as_float(m[tt*H0 + i]));
        g_T0[t] = s;
    } else if (t - NE0 < NE1) {
        int t1 = t - NE0;
        int i = t1 % H1;
        int y = (t1 / H1) % IMG;
        int b = t1 / (H1 * IMG);
        const unsigned* m = g_min1 + b * NP1;
        const float* Crow = g_C1 + y * H1;
        float s = 0.f;
        #pragma unroll 7
        for (int tt = 0; tt < H1; tt++)
            s += Crow[tt] * sqrtf(__uint_as_float(m[tt*H1 + i]));
        g_T1[t1] = s;
    }
}

// ---------------- horizontal pass + average: one block per (b, y) row ----------------
__global__ void hpass_kernel(float* __restrict__ out_mask) {
    int row = blockIdx.x;            // b*IMG + y
    int x = threadIdx.x;             // 0..223
    __shared__ float sT0[H0];
    __shared__ float sT1[H1];
    if (x < H0) sT0[x] = g_T0[row*H0 + x];
    if (x < H1) sT1[x] = g_T1[row*H1 + x];
    __syncthreads();
    const float* c0 = g_C0 + x * H0;
    const float* c1 = g_C1 + x * H1;
    float s0 = 0.f, s1 = 0.f;
    #pragma unroll 7
    for (int i = 0; i < H0; i++) s0 += c0[i] * sT0[i];
    #pragma unroll 7
    for (int j = 0; j < H1; j++) s1 += c1[j] * sT1[j];
    out_mask[row * IMG + x] = 0.5f * (s0 + s1);
}

// ---------------- launch ----------------
extern "C" void kernel_launch(void* const* d_in, const int* in_sizes, int n_in,
                              void* d_out, int out_size) {
    const float* x0 = (const float*)d_in[0];
    const float* x1 = (const float*)d_in[1];
    const float* x2 = (const float*)d_in[2];
    const float* f0 = (const float*)d_in[3];
    const float* f1 = (const float*)d_in[4];
    const float* f2 = (const float*)d_in[5];
    float* out = (float*)d_out;           // [0..3] = score, [4..] = mask

    dist_kernel<<<DIST_BLKS + 2, 256>>>(x2, f2);
    select_kernel<<<Bq, 256>>>(out);
    minmap_fused<<<BLK0 + BLK1, 256>>>(x0, f0, x1, f1);
    vpass_kernel<<<(NE0 + NE1 + 255) / 256, 256>>>();
    hpass_kernel<<<Bq * IMG, IMG>>>(out + 4);
}

// round 5
// speedup vs baseline: 1.1723x; 1.1723x over previous
#include <cuda_runtime.h>
#include <math.h>

#define Bq 4
#define Nn 500
#define Dd 2048
#define Kk 50
#define H0 28
#define C0c 512
#define NP0 (H0*H0)
#define H1 14
#define C1c 1024
#define NP1 (H1*H1)
#define IMG 224
#define KS 33
#define RAD 16

#define KCH0 10
#define KPW0 5
#define KCH1 25
#define KPW1 2
#define BLK0 ((Bq*NP0*KCH0)/8)   // 3920
#define BLK1 ((Bq*NP1*KCH1)/8)   // 2450

#define DIST_BLKS ((Bq*Nn*32 + 255)/256)   // 250

// ---------------- device scratch ----------------
__device__ float    g_d2[Bq*Nn];
__device__ int      g_idx[Bq*Kk];
__device__ unsigned g_min0[Bq*NP0];  // min DISTANCE (already sqrt'ed), float bits
__device__ unsigned g_min1[Bq*NP1];
__device__ float    g_C0[IMG*H0];    // composite blur*resize operator, level 0
__device__ float    g_C1[IMG*H1];

// reflect-101 (single reflection; RAD < IMG)
__device__ __forceinline__ int reflect(int i) {
    if (i < 0) return -i;
    if (i > IMG - 1) return 2*(IMG - 1) - i;
    return i;
}

// ---------------- pairwise distances + composite-operator precompute ----------------
__global__ void dist_kernel(const float* __restrict__ x2,
                            const float* __restrict__ f2) {
    if (blockIdx.x < DIST_BLKS) {
        int gw = (blockIdx.x * blockDim.x + threadIdx.x) >> 5;
        int lane = threadIdx.x & 31;
        if (gw >= Bq * Nn) return;
        int b = gw / Nn, n = gw % Nn;
        const float4* q = (const float4*)(x2 + (size_t)b * Dd);
        const float4* f = (const float4*)(f2 + (size_t)n * Dd);
        float ss = 0.f;
        #pragma unroll
        for (int j = 0; j < 16; j++) {
            float4 a = q[lane + j*32];
            float4 c = f[lane + j*32];
            float dx = a.x - c.x, dy = a.y - c.y, dz = a.z - c.z, dw = a.w - c.w;
            ss += dx*dx + dy*dy + dz*dz + dw*dw;
        }
        #pragma unroll
        for (int o = 16; o; o >>= 1) ss += __shfl_xor_sync(0xFFFFFFFFu, ss, o);
        if (lane == 0) g_d2[gw] = ss;
        return;
    }
    // ----- operator precompute: C = Blur(33,reflect101) * BilinearUp(H->224) -----
    int lvl = blockIdx.x - DIST_BLKS;          // 0 or 1
    int H = lvl ? H1 : H0;
    float* Cm = lvl ? g_C1 : g_C0;
    int y = threadIdx.x;
    if (y >= IMG) return;
    float w[KS];
    float wsum = 0.f;
    #pragma unroll
    for (int o = 0; o < KS; o++) {
        float xx = (float)o - (float)RAD;
        w[o] = expf(-(xx*xx) / (2.0f * 4.0f * 4.0f));
        wsum += w[o];
    }
    __shared__ float sC[IMG * H0];
    float* row = sC + y * H;
    for (int i = 0; i < H; i++) row[i] = 0.f;
    float scale = (float)H / (float)IMG;
    #pragma unroll
    for (int o = 0; o < KS; o++) {
        int t = reflect(y + o - RAD);
        float fy = ((float)t + 0.5f) * scale - 0.5f;
        float f0 = floorf(fy);
        float wf = fy - f0;
        int i0 = (int)f0;
        int i0c = max(i0, 0), i1c = min(i0 + 1, H - 1);
        float ww = w[o] / wsum;
        row[i0c] += ww * (1.f - wf);
        row[i1c] += ww * wf;
    }
    for (int i = 0; i < H; i++) Cm[y * H + i] = row[i];
}

// ---------------- select top-K + score + init scratch ----------------
__global__ void select_kernel(float* __restrict__ out_score) {
    int b = blockIdx.x;
    int tid = threadIdx.x;
    __shared__ float sd[Nn];
    __shared__ float ssel[Kk];
    for (int i = tid; i < NP0; i += 256) g_min0[b*NP0 + i] = 0x7F800000u;
    for (int i = tid; i < NP1; i += 256) g_min1[b*NP1 + i] = 0x7F800000u;
    for (int n = tid; n < Nn; n += 256) sd[n] = g_d2[b*Nn + n];
    __syncthreads();
    for (int n = tid; n < Nn; n += 256) {
        float dn = sd[n];
        int r = 0;
        for (int m = 0; m < Nn; m++) {
            float dm = sd[m];
            r += (dm < dn) || (dm == dn && m < n);
        }
        if (r < Kk) { g_idx[b*Kk + r] = n; ssel[r] = sqrtf(fmaxf(dn, 0.f)); }
    }
    __syncthreads();
    if (tid == 0) {
        float s = 0.f;
        for (int i = 0; i < Kk; i++) s += ssel[i];
        out_score[b] = s / (float)Kk;
    }
}

// ---------------- min-distance maps (HBM-bound; at compulsory-bytes floor) ----------------
template<int C, int NP, int KCH, int KPW>
__device__ __forceinline__ void minmap_body(const float* __restrict__ x,
                                            const float* __restrict__ f,
                                            unsigned* __restrict__ gmin,
                                            int wid, int lane) {
    int chunk = wid % KCH;
    int pix   = (wid / KCH) % NP;
    int b     = wid / (KCH * NP);

    int nn[KPW];
    #pragma unroll
    for (int kk = 0; kk < KPW; kk++) nn[kk] = g_idx[b*Kk + chunk*KPW + kk];

    float part[KPW];
    #pragma unroll
    for (int kk = 0; kk < KPW; kk++) part[kk] = 0.f;

    constexpr int NCH = C / 512;
    #pragma unroll
    for (int cc = 0; cc < NCH; cc++) {
        const float4* xv = (const float4*)(x + ((size_t)(b*NP + pix))*C + cc*512);
        float4 xr[4];
        #pragma unroll
        for (int r = 0; r < 4; r++) xr[r] = xv[lane + r*32];
        #pragma unroll
        for (int kk = 0; kk < KPW; kk++) {
            const float4* fv = (const float4*)(f + ((size_t)nn[kk]*NP + pix)*C + cc*512);
            #pragma unroll
            for (int r = 0; r < 4; r++) {
                float4 v = fv[lane + r*32];
                float dx = v.x - xr[r].x, dy = v.y - xr[r].y;
                float dz = v.z - xr[r].z, dw = v.w - xr[r].w;
                part[kk] += dx*dx + dy*dy + dz*dz + dw*dw;
            }
        }
    }
    #pragma unroll
    for (int kk = 0; kk < KPW; kk++) {
        #pragma unroll
        for (int o = 16; o; o >>= 1)
            part[kk] += __shfl_xor_sync(0xFFFFFFFFu, part[kk], o);
    }
    float mn = part[0];
    #pragma unroll
    for (int kk = 1; kk < KPW; kk++) mn = fminf(mn, part[kk]);
    if (lane == 0)
        atomicMin(gmin + b*NP + pix, __float_as_uint(sqrtf(mn)));  // sqrt folded here
}

__global__ void minmap_fused(const float* __restrict__ x0, const float* __restrict__ f0,
                             const float* __restrict__ x1, const float* __restrict__ f1) {
    int lane = threadIdx.x & 31;
    int wIn  = threadIdx.x >> 5;
    if (blockIdx.x < BLK0) {
        int wid = blockIdx.x * 8 + wIn;
        minmap_body<C0c, NP0, KCH0, KPW0>(x0, f0, g_min0, wid, lane);
    } else {
        int wid = (blockIdx.x - BLK0) * 8 + wIn;
        minmap_body<C1c, NP1, KCH1, KPW1>(x1, f1, g_min1, wid, lane);
    }
}

// ---------------- fused tail: resize+avg+blur as two smem contractions ----------------
// one block per output row (b, y); 896 blocks, 224 threads
__global__ void tail_kernel(float* __restrict__ out_mask) {
    int row = blockIdx.x;            // b*IMG + y
    int b = row / IMG;
    int y = row % IMG;
    int x = threadIdx.x;             // 0..223

    __shared__ float sm0[NP0];
    __shared__ float sm1[NP1];
    __shared__ float T0[H0];
    __shared__ float T1[H1];

    const unsigned* m0 = g_min0 + b * NP0;
    const unsigned* m1 = g_min1 + b * NP1;
    #pragma unroll
    for (int i = x; i < NP0; i += IMG) sm0[i] = __uint_as_float(m0[i]);
    if (x < NP1) sm1[x] = __uint_as_float(m1[x]);
    __syncthreads();

    // vertical contraction: T[i] = sum_t C[y,t] * m[t,i]
    if (x < H0) {
        const float* Crow = g_C0 + y * H0;
        float s = 0.f;
        #pragma unroll
        for (int t = 0; t < H0; t++) s += Crow[t] * sm0[t*H0 + x];
        T0[x] = s;
    } else if (x >= 32 && x < 32 + H1) {
        int j = x - 32;
        const float* Crow = g_C1 + y * H1;
        float s = 0.f;
        #pragma unroll
        for (int t = 0; t < H1; t++) s += Crow[t] * sm1[t*H1 + j];
        T1[j] = s;
    }
    __syncthreads();

    // horizontal contraction + average
    const float* c0 = g_C0 + x * H0;
    const float* c1 = g_C1 + x * H1;
    float s0 = 0.f, s1 = 0.f;
    #pragma unroll
    for (int i = 0; i < H0; i++) s0 += c0[i] * T0[i];
    #pragma unroll
    for (int j = 0; j < H1; j++) s1 += c1[j] * T1[j];
    out_mask[row * IMG + x] = 0.5f * (s0 + s1);
}

// ---------------- launch ----------------
extern "C" void kernel_launch(void* const* d_in, const int* in_sizes, int n_in,
                              void* d_out, int out_size) {
    const float* x0 = (const float*)d_in[0];
    const float* x1 = (const float*)d_in[1];
    const float* x2 = (const float*)d_in[2];
    const float* f0 = (const float*)d_in[3];
    const float* f1 = (const float*)d_in[4];
    const float* f2 = (const float*)d_in[5];
    float* out = (float*)d_out;           // [0..3] = score, [4..] = mask

    dist_kernel<<<DIST_BLKS + 2, 256>>>(x2, f2);
    select_kernel<<<Bq, 256>>>(out);
    minmap_fused<<<BLK0 + BLK1, 256>>>(x0, f0, x1, f1);
    tail_kernel<<<Bq * IMG, IMG>>>(out + 4);
}